// round 6
// baseline (speedup 1.0000x reference)
#include <cuda_runtime.h>
#include <math_constants.h>

// Problem constants (fixed shapes from reference)
#define KB 32          // batch
#define KT 8192        // time
#define KC 256         // channels
#define KW 21          // windows: 1 + 4 + 16
#define TILE 32        // rows per CTA
#define NQ  64         // float4 quads per row (KC/4)
#define NTHREADS 64    // 1 thread = 1 quad; every thread sees every row
#define SENT 0x7fffffff

__device__ __forceinline__ void atomic_max_f32(float* addr, float v) {
    // Order-isomorphic int trick; correct for all non-NaN floats.
    if (v >= 0.0f) {
        atomicMax(reinterpret_cast<int*>(addr), __float_as_int(v));
    } else {
        atomicMin(reinterpret_cast<unsigned int*>(addr), __float_as_uint(v));
    }
}

__global__ void spp_init_kernel(float* __restrict__ out, int n) {
    int i = blockIdx.x * blockDim.x + threadIdx.x;
    if (i < n) out[i] = -CUDART_INF_F;
}

__device__ __forceinline__ float4 f4max(float4 a, float4 b) {
    a.x = fmaxf(a.x, b.x);
    a.y = fmaxf(a.y, b.y);
    a.z = fmaxf(a.z, b.z);
    a.w = fmaxf(a.w, b.w);
    return a;
}
__device__ __forceinline__ float4 f4ninf() {
    return make_float4(-CUDART_INF_F, -CUDART_INF_F, -CUDART_INF_F, -CUDART_INF_F);
}

// Per-level window state machine (registers; warp-uniform except acc).
struct Win {
    int n;        // ndiv
    int dl;       // window length
    float stepf;  // (L - dl)/(n-1) in f32, matching reference exactly
    int i, s, e;  // current window index + bounds (SENT,SENT when exhausted)
    float4 acc;
};

__device__ __forceinline__ int win_start(const Win& w, int i) {
    // Exact replication of reference: round(step * i), f32, half-even.
    return (int)rintf(__fmul_rn(w.stepf, (float)i));
}

__device__ __forceinline__ void win_flush(const Win& w, float* out_lvl, int quad) {
    float* o = out_lvl + w.i * KC + quad * 4;
    atomic_max_f32(o + 0, w.acc.x);
    atomic_max_f32(o + 1, w.acc.y);
    atomic_max_f32(o + 2, w.acc.z);
    atomic_max_f32(o + 3, w.acc.w);
}

__device__ __forceinline__ void win_init(Win& w, int n, float Lf, int t0) {
    w.n = n;
    // div_len = ceil(L/n - 1e-8); 1/n mul is exact (n = 4, 16).
    float dlf = ceilf(__fmul_rn(Lf, 1.0f / (float)n) - 1e-8f);
    w.dl = (int)dlf;
    w.stepf = __fdiv_rn(Lf - dlf, (float)(n - 1));
    // Smallest i with end_i > t0 (estimate + exact fixup; loops are short).
    int i = 0;
    if (w.stepf > 0.0f) {
        i = (int)floorf(__fdiv_rn((float)(t0 - w.dl), w.stepf)) + 1;
        i = max(0, min(i, n - 1));
    }
    while (i > 0 && win_start(w, i - 1) + w.dl > t0) i--;
    while (i < n - 1 && win_start(w, i) + w.dl <= t0) i++;
    w.i = i;
    w.s = win_start(w, i);
    w.e = w.s + w.dl;
    if (w.e <= t0) { w.s = SENT; w.e = SENT; }   // defensive
    w.acc = f4ninf();
}

// All rows < t processed and t >= w.e: flush, advance to window live at t,
// back-filling already-streamed rows from L1. Handles overlaps exactly.
__device__ __forceinline__ void win_advance(Win& w, int t, int t0,
                                            const float4* __restrict__ srcq,
                                            float* out_lvl, int quad) {
    win_flush(w, out_lvl, quad);
    for (;;) {
        if (w.i >= w.n - 1) { w.s = SENT; w.e = SENT; w.acc = f4ninf(); return; }
        w.i++;
        int ns = win_start(w, w.i);
        int ne = ns + w.dl;
        float4 a = f4ninf();
        int rb = max(ns, t0), re = min(ne, t);
        for (int r = rb; r < re; r++)
            a = f4max(a, __ldg(&srcq[r * NQ]));       // L1 hits
        w.acc = a; w.s = ns; w.e = ne;
        if (ne > t) return;
        win_flush(w, out_lvl, quad);                  // tiny-L degenerate case
    }
}

// End-of-tile drain: flush current window, then any later windows starting
// before t1 (rows already streamed -> L1 back-fill).
__device__ __forceinline__ void win_drain(Win& w, int t0, int t1,
                                          const float4* __restrict__ srcq,
                                          float* out_lvl, int quad) {
    if (w.e == SENT) return;
    win_flush(w, out_lvl, quad);
    while (w.i < w.n - 1) {
        w.i++;
        int ns = win_start(w, w.i);
        if (ns >= t1) break;
        int re = min(ns + w.dl, t1);
        float4 a = f4ninf();
        for (int r = max(ns, t0); r < re; r++)
            a = f4max(a, __ldg(&srcq[r * NQ]));
        w.acc = a;
        win_flush(w, out_lvl, quad);
    }
}

__global__ __launch_bounds__(NTHREADS, 16) void spp_kernel(
    const float4* __restrict__ seq,     // [B, T, NQ]
    const int* __restrict__ lengths,    // [B]
    float* __restrict__ out)            // [B, W, C]
{
    const int b  = blockIdx.y;
    const int L  = __ldg(&lengths[b]);
    const int t0 = blockIdx.x * TILE;
    if (t0 >= L) return;
    const int t1   = min(t0 + TILE, L);
    const int quad = threadIdx.x;

    const float4* srcq = seq + (size_t)b * KT * NQ + quad;  // row r -> srcq[r*NQ]
    const float Lf = (float)L;

    float* out_b  = out + (size_t)b * KW * KC;
    float* out_l1 = out_b + 1 * KC;   // windows 1..4
    float* out_l2 = out_b + 5 * KC;   // windows 5..20

    Win w1, w2;
    win_init(w1, 4,  Lf, t0);
    win_init(w2, 16, Lf, t0);

    float4 acc0 = f4ninf();           // level-0 window [0, L) covers every tile

    int t = t0;

    // ---- FAST PATH: no window transition inside this full tile.
    // Then membership is constant -> one tile max (4 FMNMX/row), fully
    // unrolled 32 LDG.128 with immediate offsets (high MLP, zero addr ALU).
    {
        int seg = t1;
        if (w1.e < seg) seg = w1.e;
        if (w1.s > t0)  seg = min(seg, w1.s);
        if (w2.e < seg) seg = w2.e;
        if (w2.s > t0)  seg = min(seg, w2.s);
        if (seg == t1 && (t1 - t0) == TILE) {
            // FIX vs R4: base pointer rebased to row t0 (absolute rows!).
            const float4* tp = srcq + (size_t)t0 * NQ;
            float4 m = __ldg(&tp[0]);
            #pragma unroll
            for (int r = 1; r < TILE; r++)
                m = f4max(m, __ldg(&tp[r * NQ]));
            acc0 = f4max(acc0, m);
            if (t0 >= w1.s) w1.acc = f4max(w1.acc, m);
            if (t0 >= w2.s) w2.acc = f4max(w2.acc, m);
            t = t1;   // transitions at exactly t1 are handled by win_drain
        }
    }

    // ---- SLOW PATH: segmented exact streaming (boundary / edge tiles).
    while (t < t1) {
        int seg = t1;
        if (w1.e < seg) seg = w1.e;
        if (w1.s > t)   seg = min(seg, w1.s);
        if (w2.e < seg) seg = w2.e;
        if (w2.s > t)   seg = min(seg, w2.s);

        const bool in1 = (t >= w1.s);
        const bool in2 = (t >= w2.s);
        float4 a0 = acc0, a1 = w1.acc, a2 = w2.acc;
        #pragma unroll 4
        for (int r = t; r < seg; r++) {
            float4 v = __ldg(&srcq[r * NQ]);
            a0 = f4max(a0, v);
            if (in1) a1 = f4max(a1, v);
            if (in2) a2 = f4max(a2, v);
        }
        acc0 = a0; w1.acc = a1; w2.acc = a2;

        t = seg;
        if (t < t1) {   // transitions at t1 handled by drain
            if (t >= w1.e) win_advance(w1, t, t0, srcq, out_l1, quad);
            if (t >= w2.e) win_advance(w2, t, t0, srcq, out_l2, quad);
        }
    }

    win_drain(w1, t0, t1, srcq, out_l1, quad);
    win_drain(w2, t0, t1, srcq, out_l2, quad);

    // Level-0 flush (window 0).
    float* o0 = out_b + quad * 4;
    atomic_max_f32(o0 + 0, acc0.x);
    atomic_max_f32(o0 + 1, acc0.y);
    atomic_max_f32(o0 + 2, acc0.z);
    atomic_max_f32(o0 + 3, acc0.w);
}

extern "C" void kernel_launch(void* const* d_in, const int* in_sizes, int n_in,
                              void* d_out, int out_size) {
    const float4* seq     = (const float4*)d_in[0];
    const int*    lengths = (const int*)d_in[1];
    float*        out     = (float*)d_out;

    // Initialize output to -inf (harness poisons it to 0xAA before timing).
    spp_init_kernel<<<(out_size + 255) / 256, 256>>>(out, out_size);

    dim3 grid(KT / TILE, KB);
    spp_kernel<<<grid, NTHREADS>>>(seq, lengths, out);
}